// round 17
// baseline (speedup 1.0000x reference)
#include <cuda_runtime.h>
#include <cuda_bf16.h>
#include <math.h>
#include <float.h>
#include <stdint.h>

#define CH 256
#define NQ 4096
#define NK 3072
#define NH 8
#define HD 32

// ---------------- scratch (no allocations allowed) ----------------
__device__ __nv_bfloat16 g_Ab[(size_t)2 * NQ * CH];       // attention out bf16 [b][n][c]
__device__ __nv_bfloat16 g_Qb[(size_t)2 * NH * NQ * HD];  // [b][h][n][d]
__device__ __nv_bfloat16 g_Kb[(size_t)2 * NH * NK * HD];  // [b][h][k][d]
__device__ __nv_bfloat16 g_Vb[(size_t)2 * NH * NK * HD];  // [b][h][k][d]
__device__ __nv_bfloat16 g_W[4 * CH * CH];                // bf16 weights: q,k,v,o

// ---------------- helpers (sm_80-level PTX only; no 'a' features) ----------
__device__ __forceinline__ uint32_t smem_u32(const void* p) {
    uint32_t a;
    asm("{ .reg .u64 t; cvta.to.shared.u64 t, %1; cvt.u32.u64 %0, t; }" : "=r"(a) : "l"(p));
    return a;
}
__device__ __forceinline__ void ldsm_x4(uint32_t* r, uint32_t addr) {
    asm volatile("ldmatrix.sync.aligned.m8n8.x4.shared.b16 {%0,%1,%2,%3}, [%4];"
        : "=r"(r[0]), "=r"(r[1]), "=r"(r[2]), "=r"(r[3]) : "r"(addr));
}
__device__ __forceinline__ void ldsm_x2(uint32_t* r, uint32_t addr) {
    asm volatile("ldmatrix.sync.aligned.m8n8.x2.shared.b16 {%0,%1}, [%2];"
        : "=r"(r[0]), "=r"(r[1]) : "r"(addr));
}
__device__ __forceinline__ void ldsm_x4_trans(uint32_t* r, uint32_t addr) {
    asm volatile("ldmatrix.sync.aligned.m8n8.x4.trans.shared.b16 {%0,%1,%2,%3}, [%4];"
        : "=r"(r[0]), "=r"(r[1]), "=r"(r[2]), "=r"(r[3]) : "r"(addr));
}
__device__ __forceinline__ void ldsm_x2_trans(uint32_t* r, uint32_t addr) {
    asm volatile("ldmatrix.sync.aligned.m8n8.x2.trans.shared.b16 {%0,%1}, [%2];"
        : "=r"(r[0]), "=r"(r[1]) : "r"(addr));
}
__device__ __forceinline__ void mma16816(float* c, const uint32_t* a, const uint32_t* b) {
    asm volatile(
        "mma.sync.aligned.m16n8k16.row.col.f32.bf16.bf16.f32 "
        "{%0,%1,%2,%3}, {%4,%5,%6,%7}, {%8,%9}, {%0,%1,%2,%3};"
        : "+f"(c[0]), "+f"(c[1]), "+f"(c[2]), "+f"(c[3])
        : "r"(a[0]), "r"(a[1]), "r"(a[2]), "r"(a[3]), "r"(b[0]), "r"(b[1]));
}
__device__ __forceinline__ uint32_t packbf2(float x, float y) {
    __nv_bfloat162 v = __floats2bfloat162_rn(x, y);
    return *reinterpret_cast<uint32_t*>(&v);
}
__device__ __forceinline__ float ex2f(float x) {   // guaranteed MUFU.EX2
    float y;
    asm("ex2.approx.ftz.f32 %0, %1;" : "=f"(y) : "f"(x));
    return y;
}
__device__ __forceinline__ void cp_async16(uint32_t dst, const void* src) {
    asm volatile("cp.async.cg.shared.global [%0], [%1], 16;" :: "r"(dst), "l"(src));
}
#define CP_COMMIT() asm volatile("cp.async.commit_group;" ::: "memory")
#define CP_WAIT0()  asm volatile("cp.async.wait_group 0;" ::: "memory")

// ---------------------------------------------------------------------------
// Weight fp32 -> bf16 (all 4 weight matrices in one launch)
// ---------------------------------------------------------------------------
__global__ __launch_bounds__(256) void wconv_kernel(
    const float* __restrict__ w0, const float* __restrict__ w1,
    const float* __restrict__ w2, const float* __restrict__ w3)
{
    const float* src[4] = {w0, w1, w2, w3};
    int t = blockIdx.y;
    int i = blockIdx.x * 256 + threadIdx.x;
    float4 v = reinterpret_cast<const float4*>(src[t])[i];
    uint2 u;
    u.x = packbf2(v.x, v.y);
    u.y = packbf2(v.z, v.w);
    reinterpret_cast<uint2*>(g_W + (size_t)t * CH * CH)[i] = u;
}

// ---------------------------------------------------------------------------
// Fused QKV projection (proven). CTA = 128 thr, 32 tok x 128 outs.
// ---------------------------------------------------------------------------
#define STW 72
#define STX 40

__global__ __launch_bounds__(128) void proj_qkv(
    const float* __restrict__ s3, const float* __restrict__ s4,
    const float* __restrict__ s5,
    const float* __restrict__ qb2, const float* __restrict__ kb2,
    const float* __restrict__ vb2, float qsc)
{
    __shared__ __nv_bfloat16 Ws[128 * STW];
    __shared__ __nv_bfloat16 Xs[64 * STX];
    __shared__ float bs[128];

    const int i = blockIdx.x, oh = blockIdx.y, bb = blockIdx.z;

    const float* X; const float* bias; const __nv_bfloat16* Wsrc;
    __nv_bfloat16* dst; int ldx, outN, tokoff, tok0; float scale;
    if (i < 128)      { X = s3 + (long)bb * CH * NQ;   ldx = NQ;   tok0 = i * 32;
                        Wsrc = g_W;              bias = qb2; dst = g_Qb; outN = NQ; tokoff = 0;    scale = qsc; }
    else if (i < 192) { X = s4 + (long)bb * CH * 2048; ldx = 2048; tok0 = (i - 128) * 32;
                        Wsrc = g_W + CH * CH;    bias = kb2; dst = g_Kb; outN = NK; tokoff = 0;    scale = 1.0f; }
    else if (i < 224) { X = s5 + (long)bb * CH * 1024; ldx = 1024; tok0 = (i - 192) * 32;
                        Wsrc = g_W + CH * CH;    bias = kb2; dst = g_Kb; outN = NK; tokoff = 2048; scale = 1.0f; }
    else if (i < 288) { X = s4 + (long)bb * CH * 2048; ldx = 2048; tok0 = (i - 224) * 32;
                        Wsrc = g_W + 2 * CH * CH; bias = vb2; dst = g_Vb; outN = NK; tokoff = 0;    scale = 1.0f; }
    else              { X = s5 + (long)bb * CH * 1024; ldx = 1024; tok0 = (i - 288) * 32;
                        Wsrc = g_W + 2 * CH * CH; bias = vb2; dst = g_Vb; outN = NK; tokoff = 2048; scale = 1.0f; }

    const int tid = threadIdx.x, lane = tid & 31, w = tid >> 5;
    const int wt = (w & 1) * 16;
    const int wo = (w >> 1) * 64;
    const int r8 = lane & 7, mat = lane >> 3;

    bs[tid] = bias[oh * 128 + tid];

    float acc[8][4];
    #pragma unroll
    for (int a = 0; a < 8; a++)
        #pragma unroll
        for (int j = 0; j < 4; j++) acc[a][j] = 0.0f;

    #pragma unroll 1
    for (int c0 = 0; c0 < CH; c0 += 64) {
        __syncthreads();
        {
            const uint4* wg = reinterpret_cast<const uint4*>(
                Wsrc + (long)(oh * 128 + tid) * CH + c0);
            #pragma unroll
            for (int j = 0; j < 8; j++)
                *reinterpret_cast<uint4*>(&Ws[tid * STW + j * 8]) = wg[j];
        }
        {
            #pragma unroll
            for (int j = 0; j < 4; j++) {
                int idx = tid + j * 128;
                int c = idx >> 3, t4 = idx & 7;
                float4 v = *reinterpret_cast<const float4*>(
                    X + (long)(c0 + c) * ldx + tok0 + t4 * 4);
                uint2 u;
                u.x = packbf2(v.x, v.y);
                u.y = packbf2(v.z, v.w);
                *reinterpret_cast<uint2*>(&Xs[c * STX + t4 * 4]) = u;
            }
        }
        __syncthreads();

        #pragma unroll
        for (int ks = 0; ks < 4; ks++) {
            const int kk = ks * 16;
            uint32_t a[4];
            ldsm_x4_trans(a, smem_u32(
                &Xs[(kk + (mat >> 1) * 8 + r8) * STX + wt + (mat & 1) * 8]));
            #pragma unroll
            for (int nt = 0; nt < 4; nt++) {
                uint32_t bbf[4];
                ldsm_x4(bbf, smem_u32(
                    &Ws[(wo + nt * 16 + (mat >> 1) * 8 + r8) * STW + kk + (mat & 1) * 8]));
                mma16816(acc[nt * 2], a, bbf);
                mma16816(acc[nt * 2 + 1], a, bbf + 2);
            }
        }
    }

    const int g = lane >> 2, tg = lane & 3;
    #pragma unroll
    for (int n8 = 0; n8 < 8; n8++) {
        int ol = wo + n8 * 8 + tg * 2;
        int o = oh * 128 + ol;
        int h = o >> 5, d = o & 31;
        float b0 = bs[ol], b1 = bs[ol + 1];
        #pragma unroll
        for (int rh = 0; rh < 2; rh++) {
            int n = tokoff + tok0 + wt + rh * 8 + g;
            uint32_t pk = packbf2((acc[n8][rh * 2] + b0) * scale,
                                  (acc[n8][rh * 2 + 1] + b1) * scale);
            *reinterpret_cast<uint32_t*>(
                dst + (((long)(bb * NH + h) * outN + n) * HD + d)) = pk;
        }
    }
}

// ---------------------------------------------------------------------------
// HMMA flash attention. CTA = 128 queries (8 warps x 16 rows) for occupancy;
// grid 512 CTAs. Row sums via ones-matrix MMA (tensor pipe, no FADD chain,
// no epilogue shuffles). Bare MUFU exp2; bf16 coalesced epilogue to g_Ab.
// ---------------------------------------------------------------------------
#define ST_QK 40

__global__ __launch_bounds__(256, 3) void attn_mma_kernel()
{
    __shared__ __nv_bfloat16 Qs[128 * ST_QK];     // 10240 B
    __shared__ __nv_bfloat16 Ks[2][64 * ST_QK];   // 10240 B
    __shared__ __nv_bfloat16 Vs[2][64 * ST_QK];   // 10240 B

    const int b = blockIdx.z, h = blockIdx.y;
    const int q0 = blockIdx.x * 128;
    const int tid = threadIdx.x;
    const int wid = tid >> 5, lane = tid & 31;

    const __nv_bfloat16* Kg = g_Kb + (long)(b * NH + h) * NK * HD;
    const __nv_bfloat16* Vg = g_Vb + (long)(b * NH + h) * NK * HD;

    const int ldrow = tid >> 2, ldc = tid & 3;

    cp_async16(smem_u32(&Ks[0][ldrow * ST_QK + ldc * 8]),
               Kg + (long)ldrow * HD + ldc * 8);
    cp_async16(smem_u32(&Vs[0][ldrow * ST_QK + ldc * 8]),
               Vg + (long)ldrow * HD + ldc * 8);
    CP_COMMIT();

    {
        const uint4* qg = reinterpret_cast<const uint4*>(
            g_Qb + ((long)(b * NH + h) * NQ + q0) * HD);
        #pragma unroll
        for (int i = 0; i < 2; i++) {
            int idx = tid + i * 256;
            int row = idx >> 2, c = idx & 3;
            *reinterpret_cast<uint4*>(&Qs[row * ST_QK + c * 8]) = qg[idx];
        }
    }
    __syncthreads();

    // persistent Q A-fragments: warp owns rows wid*16..wid*16+15
    uint32_t aq[2][4];
    {
        int mat = lane >> 3, r = lane & 7;
        #pragma unroll
        for (int ks = 0; ks < 2; ks++)
            ldsm_x4(aq[ks], smem_u32(
                &Qs[(wid * 16 + (mat & 1) * 8 + r) * ST_QK
                    + ks * 16 + (mat >> 1) * 8]));
    }

    float o[4][4];
    #pragma unroll
    for (int dn = 0; dn < 4; dn++)
        #pragma unroll
        for (int j = 0; j < 4; j++) o[dn][j] = 0.0f;
    float lr[4] = {0.0f, 0.0f, 0.0f, 0.0f};   // ones-MMA row-sum accumulator

    const uint32_t onesf[2] = {0x3F803F80u, 0x3F803F80u};  // bf16 1.0 x4
    const int r8 = lane & 7;
    const int half = (lane >> 3) & 1;
    const int NT = NK / 64;

    #pragma unroll 1
    for (int t = 0; t < NT; t++) {
        CP_WAIT0();
        __syncthreads();
        if (t + 1 < NT) {
            const int nb = (t + 1) & 1;
            const long koff = (long)(t + 1) * 64 * HD;
            cp_async16(smem_u32(&Ks[nb][ldrow * ST_QK + ldc * 8]),
                       Kg + koff + (long)ldrow * HD + ldc * 8);
            cp_async16(smem_u32(&Vs[nb][ldrow * ST_QK + ldc * 8]),
                       Vg + koff + (long)ldrow * HD + ldc * 8);
            CP_COMMIT();
        }
        const __nv_bfloat16* Kt = Ks[t & 1];
        const __nv_bfloat16* Vt = Vs[t & 1];

        #pragma unroll
        for (int chnk = 0; chnk < 4; chnk++) {
            const int kb = chnk * 16;

            uint32_t bk[2][2][2];
            #pragma unroll
            for (int n = 0; n < 2; n++)
                #pragma unroll
                for (int ks = 0; ks < 2; ks++)
                    ldsm_x2(bk[n][ks], smem_u32(
                        &Kt[(kb + n * 8 + r8) * ST_QK + ks * 16 + half * 8]));

            float s[2][4];
            #pragma unroll
            for (int n = 0; n < 2; n++) {
                #pragma unroll
                for (int j = 0; j < 4; j++) s[n][j] = 0.0f;
                mma16816(s[n], aq[0], bk[n][0]);
                mma16816(s[n], aq[1], bk[n][1]);
            }

            float e0 = ex2f(s[0][0]);
            float e1 = ex2f(s[0][1]);
            float e2 = ex2f(s[0][2]);
            float e3 = ex2f(s[0][3]);
            float e4 = ex2f(s[1][0]);
            float e5 = ex2f(s[1][1]);
            float e6 = ex2f(s[1][2]);
            float e7 = ex2f(s[1][3]);
            uint32_t ap[4];
            ap[0] = packbf2(e0, e1);
            ap[1] = packbf2(e2, e3);
            ap[2] = packbf2(e4, e5);
            ap[3] = packbf2(e6, e7);

            // row sums on the tensor pipe: lr += P @ ones
            mma16816(lr, ap, onesf);

            uint32_t bv[4][2];
            #pragma unroll
            for (int dn = 0; dn < 4; dn++)
                ldsm_x2_trans(bv[dn], smem_u32(
                    &Vt[(kb + half * 8 + r8) * ST_QK + dn * 8]));

            #pragma unroll
            for (int dn = 0; dn < 4; dn++)
                mma16816(o[dn], ap, bv[dn]);
        }
        __syncthreads();
    }

    // lr[0]/lr[2] hold full row sums for rows g / g+8 (identical across quad)
    const float linv[2] = {1.0f / lr[0], 1.0f / lr[2]};

    const int g = lane >> 2, tg = lane & 3;
    __nv_bfloat16* Ap = g_Ab + (long)b * NQ * CH;
    #pragma unroll
    for (int rh = 0; rh < 2; rh++) {
        int n = q0 + wid * 16 + rh * 8 + g;
        float sc = linv[rh];
        #pragma unroll
        for (int dn = 0; dn < 4; dn++) {
            int c = h * HD + dn * 8 + tg * 2;
            uint32_t pk = packbf2(o[dn][rh * 2] * sc, o[dn][rh * 2 + 1] * sc);
            *reinterpret_cast<uint32_t*>(Ap + (long)n * CH + c) = pk;
        }
    }
}

// ---------------------------------------------------------------------------
// Fused o-proj + bias + residual + LayerNorm. CTA = 32 tokens x 256 outs.
// k-chunk 64 (4 iters, 8 barriers). Residual added via a separate COALESCED
// smem pass (was the R14 L1 hotspot). Stage buffer aliases GEMM buffers.
// ---------------------------------------------------------------------------
#define STA 264     // Xa row stride (bf16): 528B
#define STG_LN 257  // LN stage row stride (fp32)
#define RAW_BYTES 53760   // max(Xa 16896 + Ws 36864, stage 32896)

__global__ __launch_bounds__(256) void proj_o_ln(
    const float* __restrict__ ob2, const float* __restrict__ res,
    const float* __restrict__ lnw, const float* __restrict__ lnb,
    float* __restrict__ out)
{
    __shared__ __align__(16) unsigned char raw[RAW_BYTES];
    __shared__ float bs[256];
    __shared__ float smu[32], srs[32];

    __nv_bfloat16* Xa = reinterpret_cast<__nv_bfloat16*>(raw);           // [32][STA]
    __nv_bfloat16* Ws = reinterpret_cast<__nv_bfloat16*>(raw + 16896);   // [256][STW]
    float* stg = reinterpret_cast<float*>(raw);                          // [32][STG_LN]

    const int bb = blockIdx.y;
    const int tok0 = blockIdx.x * 32;
    const int tid = threadIdx.x, lane = tid & 31, w = tid >> 5;
    const int wt = (w & 1) * 16;
    const int wo = (w >> 1) * 64;
    const int r8 = lane & 7, mat = lane >> 3;

    bs[tid] = ob2[tid];

    // load Xa: [32 tok][256 c] bf16 (coalesced)
    {
        const uint4* Ag = reinterpret_cast<const uint4*>(
            g_Ab + ((long)bb * NQ + tok0) * CH);
        #pragma unroll
        for (int j = 0; j < 4; j++) {
            int idx = tid + j * 256;
            int row = idx >> 5, cc = idx & 31;
            *reinterpret_cast<uint4*>(&Xa[row * STA + cc * 8]) = Ag[idx];
        }
    }

    float acc[8][4];
    #pragma unroll
    for (int a = 0; a < 8; a++)
        #pragma unroll
        for (int j = 0; j < 4; j++) acc[a][j] = 0.0f;

    const __nv_bfloat16* Wsrc = g_W + 3 * CH * CH;

    #pragma unroll 1
    for (int c0 = 0; c0 < CH; c0 += 64) {
        __syncthreads();
        {
            const uint4* wg = reinterpret_cast<const uint4*>(
                Wsrc + (long)tid * CH + c0);
            #pragma unroll
            for (int j = 0; j < 8; j++)
                *reinterpret_cast<uint4*>(&Ws[tid * STW + j * 8]) = wg[j];
        }
        __syncthreads();

        #pragma unroll
        for (int ks = 0; ks < 4; ks++) {
            const int kk = ks * 16;
            uint32_t a[4];
            ldsm_x4(a, smem_u32(
                &Xa[(wt + (mat & 1) * 8 + r8) * STA + c0 + kk + (mat >> 1) * 8]));
            #pragma unroll
            for (int nt = 0; nt < 4; nt++) {
                uint32_t bbf[4];
                ldsm_x4(bbf, smem_u32(
                    &Ws[(wo + nt * 16 + (mat >> 1) * 8 + r8) * STW + kk + (mat & 1) * 8]));
                mma16816(acc[nt * 2], a, bbf);
                mma16816(acc[nt * 2 + 1], a, bbf + 2);
            }
        }
    }

    // ---- stage acc + bias ----
    __syncthreads();
    const int g = lane >> 2, tg = lane & 3;
    #pragma unroll
    for (int n8 = 0; n8 < 8; n8++) {
        int ol = wo + n8 * 8 + tg * 2;
        #pragma unroll
        for (int rh = 0; rh < 2; rh++) {
            int n = wt + rh * 8 + g;
            stg[n * STG_LN + ol]     = acc[n8][rh * 2]     + bs[ol];
            stg[n * STG_LN + ol + 1] = acc[n8][rh * 2 + 1] + bs[ol + 1];
        }
    }
    __syncthreads();

    // ---- coalesced residual add (warp reads 128B rows of res) ----
    const int nn = tid & 31, cb = tid >> 5;
    #pragma unroll
    for (int i = 0; i < 32; i++) {
        int c = cb + i * 8;
        stg[nn * STG_LN + c] += res[((long)bb * CH + c) * NQ + tok0 + nn];
    }
    __syncthreads();

    // ---- LN reduce: warp w owns tokens w*4 .. w*4+3 ----
    #pragma unroll
    for (int tt = 0; tt < 4; tt++) {
        int t = w * 4 + tt;
        float sum = 0.0f, sq = 0.0f;
        #pragma unroll
        for (int j = 0; j < 8; j++) {
            float x = stg[t * STG_LN + lane + j * 32];
            sum += x; sq += x * x;
        }
        #pragma unroll
        for (int off = 16; off > 0; off >>= 1) {
            sum += __shfl_xor_sync(0xFFFFFFFFu, sum, off);
            sq  += __shfl_xor_sync(0xFFFFFFFFu, sq, off);
        }
        if (lane == 0) {
            float mu = sum * (1.0f / CH);
            float var = sq * (1.0f / CH) - mu * mu;
            smu[t] = mu;
            srs[t] = rsqrtf(var + 1e-5f);
        }
    }
    __syncthreads();

    // ---- write out [b][c][n], coalesced over n ----
    float mu = smu[nn], rs = srs[nn];
    #pragma unroll
    for (int i = 0; i < 32; i++) {
        int c = cb + i * 8;
        float v = (stg[nn * STG_LN + c] - mu) * rs * lnw[c] + lnb[c];
        out[((long)bb * CH + c) * NQ + tok0 + nn] = v;
    }
}

// ---------------------------------------------------------------------------
extern "C" void kernel_launch(void* const* d_in, const int* in_sizes, int n_in,
                              void* d_out, int out_size)
{
    const float* s3  = (const float*)d_in[0];
    const float* s4  = (const float*)d_in[1];
    const float* s5  = (const float*)d_in[2];
    const float* qw  = (const float*)d_in[3];
    const float* qb  = (const float*)d_in[4];
    const float* kw  = (const float*)d_in[5];
    const float* kb  = (const float*)d_in[6];
    const float* vw  = (const float*)d_in[7];
    const float* vb  = (const float*)d_in[8];
    const float* ow  = (const float*)d_in[9];
    const float* ob  = (const float*)d_in[10];
    const float* lnw = (const float*)d_in[11];
    const float* lnb = (const float*)d_in[12];
    float* out = (float*)d_out;

    // 32^-0.5 * log2(e)  (exp2-based softmax)
    const float qscale = 0.17677669529663689f * 1.4426950408889634f;

    wconv_kernel<<<dim3(CH * CH / 1024, 4), 256>>>(qw, kw, vw, ow);
    proj_qkv<<<dim3(320, 2, 2), 128>>>(s3, s4, s5, qb, kb, vb, qscale);
    attn_mma_kernel<<<dim3(NQ / 128, NH, 2), 256>>>();
    proj_o_ln<<<dim3(NQ / 32, 2), 256>>>(ob, s3, lnw, lnb, out);
}